// round 16
// baseline (speedup 1.0000x reference)
#include <cuda_runtime.h>
#include <math.h>
#include <stdint.h>

// Problem dims
#define T_DIM 4096
#define B_DIM 512
#define NSTEP 4095                  // scan steps (t = 1..4095)
#define NELEM (T_DIM * B_DIM)       // 2,097,152
#define PREP_BLOCKS (NELEM / 256)   // 8192
#define WIN 8
#define NWIN 512                    // window 511 has 7 real steps + 1 dummy
#define PROWS 4120                  // padded: LDG ring + L2 prefetch stay in-bounds
#define PL ((size_t)PROWS * B_DIM)

#define BARRIER() asm volatile("bar.sync 0;" ::: "memory")
#define PREFETCH_L2(p) asm volatile("prefetch.global.L2 [%0];" :: "l"(p))

// ---------------------------------------------------------------------------
// Stage-specific coefficient planes, [step][b] (coalesced). Rows >= 4095
// stay zero (benign dummy step).
//   pM0 = (C1', C2', C3', C4')      Ci' = tau*Ci
//   pM1 = (A',  mn, mx, kThz)       A'  = 1 + tau*((-2*damp)*tau2); kThz=kTh*tau/mB
//   pR0 = (e1, e2, -u1, u2)
//   pR1 = (kThd1, kThd2, e3, -kToz)
//   pQ  = (Cd', label)
// ---------------------------------------------------------------------------
__device__ float4 g_pM0[PL], g_pM1[PL], g_pR0[PL], g_pR1[PL];
__device__ float2 g_pQ[PL];
__device__ float  g_part[PREP_BLOCKS];
__device__ float  g_hover;
__device__ double g_loss[B_DIM];

__device__ __forceinline__ float sc(float g, float base) {
    float t = (0.5f - g) * 95.0f;
    t = t / 100.0f;
    return (1.0f + t) * base;
}

// ---------------------------------------------------------------------------
// Kernel 1: precompute folded coefficients + partial sums of kTh (for hover)
// ---------------------------------------------------------------------------
__global__ void __launch_bounds__(256) prep_kernel(
    const float* __restrict__ logits,
    const float* __restrict__ u1p, const float* __restrict__ u2p,
    const float* __restrict__ u3p, const float* __restrict__ u4p,
    const float* __restrict__ maxp, const float* __restrict__ minp,
    const float* __restrict__ lab)
{
    const int idx = blockIdx.x * 256 + threadIdx.x;
    const float4* lg = reinterpret_cast<const float4*>(logits) + (size_t)idx * 3;
    float4 l0 = lg[0];
    float4 l1 = lg[1];
    float4 l2 = lg[2];

    float kTh = sc(l1.w, 1.076e-05f);

    // shuffle-based block reduction of kTh
    {
        float v = kTh;
        #pragma unroll
        for (int o = 16; o; o >>= 1) v += __shfl_down_sync(0xffffffffu, v, o);
        __shared__ float wpart[8];
        if ((threadIdx.x & 31) == 0) wpart[threadIdx.x >> 5] = v;
        __syncthreads();
        if (threadIdx.x < 8) {
            float s = wpart[threadIdx.x];
            #pragma unroll
            for (int o = 4; o; o >>= 1) s += __shfl_down_sync(0xffu, s, o);
            if (threadIdx.x == 0) g_part[blockIdx.x] = s;
        }
    }

    const int t = idx >> 9;
    const int b = idx & 511;
    if (t >= 1) {
        const float tau = 0.005f;
        const float TM  = (float)(0.005 / 1.2);   // tau / mB
        const float UPT = (float)(1e-4 * 0.005);  // uP*IRzz*tau

        float dxm  = sc(l0.x, 0.16f);
        float dym  = sc(l0.y, 0.16f);
        float IBxx = sc(l0.w, 0.0123f);
        float IByy = sc(l1.x, 0.0123f);
        float IBzz = sc(l1.y, 0.0123f);
        float Cd   = sc(l1.z, 0.1f);
        float kTo  = sc(l2.x, 1.632e-07f);
        float tau2 = sc(l2.y, 0.015f);
        float kp   = sc(l2.z, 1.0f);
        float damp = sc(l2.w, 1.0f);

        float A    = (-2.0f * damp) * tau2;
        float Ap   = fmaf(tau, A, 1.0f);          // A' = 1 + tau*A
        float rt2s = __fdividef(1.0f, tau2 * tau2);
        float C1 = tau * ((kp * u1p[idx]) * rt2s);
        float C2 = tau * ((kp * u2p[idx]) * rt2s);
        float C3 = tau * ((kp * u3p[idx]) * rt2s);
        float C4 = tau * ((kp * u4p[idx]) * rt2s);

        float rx = __fdividef(1.0f, IBxx);
        float ry = __fdividef(1.0f, IByy);
        float rz = __fdividef(1.0f, IBzz);

        float Cdz   = Cd * TM;
        float kThz  = kTh * TM;
        float kThd1 = ((kTh * dym) * tau) * rx;
        float kThd2 = ((kTh * dxm) * tau) * ry;
        float e1 = ((IByy - IBzz) * tau) * rx;
        float u1 = UPT * rx;
        float e2 = ((IBzz - IBxx) * tau) * ry;
        float u2 = UPT * ry;
        float e3 = ((IBxx - IByy) * tau) * rz;
        float kToz = (kTo * tau) * rz;

        size_t o = (size_t)(t - 1) * B_DIM + b;
        g_pM0[o]  = make_float4(C1, C2, C3, C4);
        g_pM1[o]  = make_float4(Ap, minp[idx], maxp[idx], kThz);
        g_pR0[o]  = make_float4(e1, e2, -u1, u2);
        g_pR1[o]  = make_float4(kThd1, kThd2, e3, -kToz);
        g_pQ[o]   = make_float2(Cdz, lab[idx]);
    }
}

// ---------------------------------------------------------------------------
// Kernel 2: hover = sqrt(max(mB*g/(4*mean(kTh)+eps), 1e-6))
// ---------------------------------------------------------------------------
__global__ void hover_kernel()
{
    __shared__ double red[256];
    double s = 0.0;
    for (int i = threadIdx.x; i < PREP_BLOCKS; i += 256) s += (double)g_part[i];
    red[threadIdx.x] = s;
    __syncthreads();
    #pragma unroll
    for (int st = 128; st > 0; st >>= 1) {
        if (threadIdx.x < st) red[threadIdx.x] += red[threadIdx.x + st];
        __syncthreads();
    }
    if (threadIdx.x == 0) {
        float m   = (float)(red[0] / (double)NELEM);
        float den = 4.0f * m + 1e-12f;
        float v   = (float)(1.2 * 9.81) / den;
        v = fmaxf(v, 1e-6f);
        g_hover = sqrtf(v);
    }
}

// ---------------------------------------------------------------------------
// Kernel 3: warp-specialized 6-warp pipeline, SMSP-load-balanced.
// 16 blocks x 192 threads.  SMSP = wid % 4:
//   SMSP0: wid0 M12 (motors 1,2)  + wid4 M34 (motors 3,4)   ~24 ops/step
//   SMSP1: wid1 Sums/Thr          + wid5 z/loss             ~30 ops/step
//   SMSP2: wid2 Rates                                       ~18 ops/step
//   SMSP3: wid3 Quaternion                                  ~16 ops/step
// Same window skews as R12/R15; rel_err bit-identical.
// ---------------------------------------------------------------------------
__global__ void __launch_bounds__(192, 1) sim_kernel(const float* __restrict__ labels)
{
    const int wid  = threadIdx.x >> 5;
    const int lane = threadIdx.x & 31;
    const int b    = blockIdx.x * 32 + lane;

    const float tau = 0.005f;
    const float HT  = 0.0025f;   // tau * 0.5
    const float GT  = 0.04905f;  // g * tau

    __shared__ float2 sWa[2][WIN][32];  // (w1c,w2c)        M12 -> Sums
    __shared__ float2 sWb[2][WIN][32];  // (w3c,w4c)        M34 -> Sums
    __shared__ float4 sS[2][WIN][32];   // spp,smm,sqn,wsum Sums -> Rates
    __shared__ float  sT[4][WIN][32];   // Thr              Sums -> z/loss (3-win hop)
    __shared__ float4 sH[2][WIN][32];   // hp,hq,hr,0       Rates -> Quat
    __shared__ float4 sQ[2][WIN][32];   // pre-update q     Quat -> z/loss

    // batched prefetch bases (block-segment addressing)
    const char* pfM0 = (const char*)(g_pM0 + blockIdx.x * 32);
    const char* pfM1 = (const char*)(g_pM1 + blockIdx.x * 32);
    const char* pfR0 = (const char*)(g_pR0 + blockIdx.x * 32);
    const char* pfR1 = (const char*)(g_pR1 + blockIdx.x * 32);
    const char* pfQ  = (const char*)(g_pQ + blockIdx.x * 32);
    #define PF_F4(base, s0) PREFETCH_L2((base) + \
        (size_t)((s0) + 2 * WIN + (lane >> 2)) * 8192 + (size_t)(lane & 3) * 128)
    #define PF_F2(base, s0) if (lane < 16) PREFETCH_L2((base) + \
        (size_t)((s0) + 2 * WIN + (lane >> 1)) * 4096 + (size_t)(lane & 1) * 128)

    if (wid == 0 || wid == 4) {
        // ============ Motors: wid0 -> motors 1,2 ; wid4 -> motors 3,4 ======
        const bool hi = (wid == 4);      // true: motors 3,4
        const float hover = g_hover;
        float wA = hover, wB = hover;    // (w1,w2) or (w3,w4)
        float dA = 0.f, dB = 0.f;        // (wd1,wd2) or (wd3,wd4)
        const float4* __restrict__ PM0 = g_pM0 + b;
        const float4* __restrict__ PM1 = g_pM1 + b;
        float4 bm0[WIN], bm1[WIN];
        #pragma unroll
        for (int j = 0; j < WIN; ++j) {
            bm0[j] = PM0[(size_t)j * B_DIM];
            bm1[j] = PM1[(size_t)j * B_DIM];
        }
        for (int p = 0; p < NWIN + 4; ++p) {
            if (p < NWIN) {
                const int s0  = p * WIN;
                const int par = p & 1;
                if (!hi) { PF_F4(pfM0, s0); } else { PF_F4(pfM1, s0); }
                #pragma unroll
                for (int j = 0; j < WIN; ++j) {
                    const float4 c0 = bm0[j];   // C1'..C4'
                    const float4 c1 = bm1[j];   // A', mn, mx, kThz
                    const float cA = hi ? c0.z : c0.x;
                    const float cB = hi ? c0.w : c0.y;
                    // nwd = A'*wd + (C' - tau*w)   [uses pre-clip w]
                    float tA = fmaf(-tau, wA, cA);
                    float tB = fmaf(-tau, wB, cB);

                    float wAc = fminf(fmaxf(wA, c1.y), c1.z);
                    float wBc = fminf(fmaxf(wB, c1.y), c1.z);

                    if (!hi) sWa[par][j][lane] = make_float2(wAc, wBc);
                    else     sWb[par][j][lane] = make_float2(wAc, wBc);

                    wA = fmaf(tau, dA, wAc);
                    wB = fmaf(tau, dB, wBc);
                    dA = fmaf(c1.x, dA, tA);
                    dB = fmaf(c1.x, dB, tB);

                    bm0[j] = PM0[(size_t)(s0 + WIN + j) * B_DIM];
                    bm1[j] = PM1[(size_t)(s0 + WIN + j) * B_DIM];
                }
            }
            BARRIER();
        }
    } else if (wid == 1) {
        // ================= Sums / Thr (window p-1) =================
        const float4* __restrict__ PM1 = g_pM1 + b;   // kThz in .w (L2/L1-hot)
        float4 bk[WIN];
        #pragma unroll
        for (int j = 0; j < WIN; ++j) bk[j] = PM1[(size_t)j * B_DIM];
        for (int p = 0; p < NWIN + 4; ++p) {
            if (p >= 1 && p <= NWIN) {
                const int w    = p - 1;
                const int s0   = w * WIN;
                const int par  = w & 1;
                const int par4 = w & 3;
                float2 wva[WIN], wvb[WIN];
                #pragma unroll
                for (int j = 0; j < WIN; ++j) {
                    wva[j] = sWa[par][j][lane];
                    wvb[j] = sWb[par][j][lane];
                }
                #pragma unroll
                for (int j = 0; j < WIN; ++j) {
                    const float w1c = wva[j].x, w2c = wva[j].y;
                    const float w3c = wvb[j].x, w4c = wvb[j].y;
                    float s1 = w1c * w1c, s2 = w2c * w2c;
                    float s3 = w3c * w3c, s4 = w4c * w4c;
                    float a12 = s1 + s2, a34 = s3 + s4;
                    float d12 = s1 - s2, d34 = s3 - s4;
                    float sa  = a12 + a34;
                    float spp = a12 - a34;
                    float smm = d12 - d34;
                    float sqn = d12 + d34;
                    float wsum = (w1c - w2c) + (w3c - w4c);
                    float Thr = bk[j].w * sa;

                    sS[par][j][lane]  = make_float4(spp, smm, sqn, wsum);
                    sT[par4][j][lane] = Thr;

                    bk[j] = PM1[(size_t)(s0 + WIN + j) * B_DIM];
                }
            }
            BARRIER();
        }
    } else if (wid == 2) {
        // ================= Body rates (window p-2) =================
        float pv = 0.f, qv = 0.f, rv = 0.f;
        const float4* __restrict__ PR0 = g_pR0 + b;
        const float4* __restrict__ PR1 = g_pR1 + b;
        float4 br0[WIN], br1[WIN];
        #pragma unroll
        for (int j = 0; j < WIN; ++j) {
            br0[j] = PR0[(size_t)j * B_DIM];
            br1[j] = PR1[(size_t)j * B_DIM];
        }
        for (int p = 0; p < NWIN + 4; ++p) {
            if (p >= 2 && p <= NWIN + 1) {
                const int w   = p - 2;
                const int s0  = w * WIN;
                const int par = w & 1;
                PF_F4(pfR0, s0);
                PF_F4(pfR1, s0);
                float4 m[WIN];
                #pragma unroll
                for (int j = 0; j < WIN; ++j) m[j] = sS[par][j][lane];
                #pragma unroll
                for (int j = 0; j < WIN; ++j) {
                    const float4 r0 = br0[j];   // e1, e2, -u1, u2
                    const float4 r1 = br1[j];   // kThd1, kThd2, e3, -kToz
                    const float4 mm = m[j];     // spp, smm, sqn, wsum

                    float qvrv = qv * rv, pvrv = pv * rv, pvqv = pv * qv;
                    float wq = mm.w * qv, wp = mm.w * pv;

                    float t1 = r0.x * qvrv;
                    t1 = fmaf(r0.z, wq, t1);
                    t1 = fmaf(r1.x, mm.y, t1);
                    float npv = pv + t1;

                    float t2 = r0.y * pvrv;
                    t2 = fmaf(r0.w, wp, t2);
                    t2 = fmaf(r1.y, mm.x, t2);
                    float nqv = qv + t2;

                    float t3 = r1.z * pvqv;
                    t3 = fmaf(r1.w, mm.z, t3);
                    float nrv = rv + t3;

                    // half-rates from CURRENT (pre-update) state
                    float hp = HT * pv, hq = HT * qv, hr = HT * rv;
                    sH[par][j][lane] = make_float4(hp, hq, hr, 0.f);

                    pv = npv; qv = nqv; rv = nrv;

                    br0[j] = PR0[(size_t)(s0 + WIN + j) * B_DIM];
                    br1[j] = PR1[(size_t)(s0 + WIN + j) * B_DIM];
                }
            }
            BARRIER();
        }
    } else if (wid == 3) {
        // ================= Quaternion (window p-3) =================
        float q0 = 1.f, q1 = 0.f, q2 = 0.f, q3 = 0.f;
        for (int p = 0; p < NWIN + 4; ++p) {
            if (p >= 3 && p <= NWIN + 2) {
                const int w   = p - 3;
                const int par = w & 1;
                float4 h[WIN];
                #pragma unroll
                for (int j = 0; j < WIN; ++j) h[j] = sH[par][j][lane];
                #pragma unroll
                for (int j = 0; j < WIN; ++j) {
                    const float hp = h[j].x, hq = h[j].y, hr = h[j].z;

                    // pre-update q goes to z/loss (z-dynamics uses carry q)
                    sQ[par][j][lane] = make_float4(q0, q1, q2, q3);

                    float tA0 = fmaf(-hr, q3, fmaf(-hq, q2, (-hp) * q1));
                    float tA2 = fmaf(-hr, q1, fmaf( hq, q0,   hp  * q3));
                    float tB1 = fmaf( hr, q2, fmaf(-hq, q3,   hp  * q0));
                    float tB3 = fmaf( hr, q0, fmaf( hq, q1, (-hp) * q2));
                    float nq0 = q0 + tA0;
                    float nq2 = q2 + tA2;
                    float nq1 = q1 + tB1;
                    float nq3 = q3 + tB3;
                    q0 = nq0; q1 = nq1; q2 = nq2; q3 = nq3;
                }
            }
            BARRIER();
        }
    } else {
        // ================= z / loss (window p-4), wid == 5 =================
        float xz = 0.f, zd = 0.f;
        const float2* __restrict__ PQ = g_pQ + b;
        float2 bq[WIN];
        #pragma unroll
        for (int j = 0; j < WIN; ++j) bq[j] = PQ[(size_t)j * B_DIM];
        double acc;
        { float l0 = labels[b]; acc = (double)l0 * (double)l0; }
        for (int p = 0; p < NWIN + 4; ++p) {
            if (p >= 4) {
                const int w    = p - 4;
                const int s0   = w * WIN;
                const int par  = w & 1;
                const int par4 = w & 3;
                PF_F2(pfQ, s0);
                float4 qv4[WIN];
                float  thr[WIN];
                #pragma unroll
                for (int j = 0; j < WIN; ++j) {
                    qv4[j] = sQ[par][j][lane];
                    thr[j] = sT[par4][j][lane];
                }
                float accf = 0.f;
                #pragma unroll
                for (int j = 0; j < WIN; ++j) {
                    const float2 qc = bq[j];        // Cd', label
                    const float4 qd = qv4[j];
                    const float Thr = thr[j];

                    float sq0 = qd.x * qd.x, sq1 = qd.y * qd.y;
                    float sq2 = qd.z * qd.z, sq3 = qd.w * qd.w;
                    float qq = (sq0 - sq1) - (sq2 - sq3);

                    float zd2 = zd * zd;
                    float sz = (zd > 0.f) ? 1.f : ((zd < 0.f) ? -1.f : 0.f);
                    float drag = qc.x * (sz * zd2);
                    float nzd = zd + ((Thr * qq - drag) - GT);

                    float nxz_raw = fmaf(tau, nzd, xz);
                    float diff = nxz_raw - xz;
                    float nxz = (fabsf(diff) <= 400.0f) ? nxz_raw : xz;

                    float dz = nxz - qc.y;
                    if (s0 + j < NSTEP) accf = fmaf(dz, dz, accf);

                    xz = nxz; zd = nzd;

                    bq[j] = PQ[(size_t)(s0 + WIN + j) * B_DIM];
                }
                acc += (double)accf;
            }
            BARRIER();
        }
        g_loss[b] = acc;
    }
    #undef PF_F4
    #undef PF_F2
}

// ---------------------------------------------------------------------------
// Kernel 4: deterministic loss reduction -> mean
// ---------------------------------------------------------------------------
__global__ void loss_kernel(float* __restrict__ out)
{
    __shared__ double red[B_DIM];
    red[threadIdx.x] = g_loss[threadIdx.x];
    __syncthreads();
    #pragma unroll
    for (int s = 256; s > 0; s >>= 1) {
        if (threadIdx.x < s) red[threadIdx.x] += red[threadIdx.x + s];
        __syncthreads();
    }
    if (threadIdx.x == 0) out[0] = (float)(red[0] / (double)NELEM);
}

// ---------------------------------------------------------------------------
// Launch
// ---------------------------------------------------------------------------
extern "C" void kernel_launch(void* const* d_in, const int* in_sizes, int n_in,
                              void* d_out, int out_size)
{
    const float* labels = (const float*)d_in[0];
    const float* logits = (const float*)d_in[1];
    const float* u1     = (const float*)d_in[2];
    const float* u2     = (const float*)d_in[3];
    const float* u3     = (const float*)d_in[4];
    const float* u4     = (const float*)d_in[5];
    const float* maxM   = (const float*)d_in[6];
    const float* minM   = (const float*)d_in[7];

    prep_kernel<<<PREP_BLOCKS, 256>>>(logits, u1, u2, u3, u4, maxM, minM, labels);
    hover_kernel<<<1, 256>>>();
    sim_kernel<<<16, 192>>>(labels);
    loss_kernel<<<1, B_DIM>>>((float*)d_out);
}

// round 17
// speedup vs baseline: 1.0952x; 1.0952x over previous
#include <cuda_runtime.h>
#include <math.h>
#include <stdint.h>

// Problem dims
#define T_DIM 4096
#define B_DIM 512
#define NSTEP 4095                  // scan steps (t = 1..4095)
#define NELEM (T_DIM * B_DIM)       // 2,097,152
#define PREP_BLOCKS (NELEM / 256)   // 8192
#define WIN 8
#define NWIN 512                    // window 511 has 7 real steps + 1 dummy
#define PROWS 4120                  // padded: LDG ring + L2 prefetch stay in-bounds
#define PL ((size_t)PROWS * B_DIM)

#define BARRIER() asm volatile("bar.sync 0;" ::: "memory")
#define PREFETCH_L2(p) asm volatile("prefetch.global.L2 [%0];" :: "l"(p))

// ---------------------------------------------------------------------------
// Stage-specific coefficient planes, [step][b] (coalesced). Rows >= 4095
// stay zero (benign dummy step).
//   pM0 = (C1', C2', C3', C4')      Ci' = tau*Ci
//   pM1 = (A',  mn, mx, kThz)       A'  = 1 + tau*((-2*damp)*tau2); kThz=kTh*tau/mB
//   pR0 = (e1, e2, -u1, u2)
//   pR1 = (kThd1, kThd2, e3, -kToz)
//   pQ  = (Cd', label)
// ---------------------------------------------------------------------------
__device__ float4 g_pM0[PL], g_pM1[PL], g_pR0[PL], g_pR1[PL];
__device__ float2 g_pQ[PL];
__device__ float  g_part[PREP_BLOCKS];
__device__ float  g_hover;
__device__ double g_loss[B_DIM];

__device__ __forceinline__ float sc(float g, float base) {
    float t = (0.5f - g) * 95.0f;
    t = t / 100.0f;
    return (1.0f + t) * base;
}

// ---------------------------------------------------------------------------
// Kernel 1: precompute folded coefficients + partial sums of kTh (for hover)
// ---------------------------------------------------------------------------
__global__ void __launch_bounds__(256) prep_kernel(
    const float* __restrict__ logits,
    const float* __restrict__ u1p, const float* __restrict__ u2p,
    const float* __restrict__ u3p, const float* __restrict__ u4p,
    const float* __restrict__ maxp, const float* __restrict__ minp,
    const float* __restrict__ lab)
{
    const int idx = blockIdx.x * 256 + threadIdx.x;
    const float4* lg = reinterpret_cast<const float4*>(logits) + (size_t)idx * 3;
    float4 l0 = lg[0];
    float4 l1 = lg[1];
    float4 l2 = lg[2];

    float kTh = sc(l1.w, 1.076e-05f);

    // shuffle-based block reduction of kTh
    {
        float v = kTh;
        #pragma unroll
        for (int o = 16; o; o >>= 1) v += __shfl_down_sync(0xffffffffu, v, o);
        __shared__ float wpart[8];
        if ((threadIdx.x & 31) == 0) wpart[threadIdx.x >> 5] = v;
        __syncthreads();
        if (threadIdx.x < 8) {
            float s = wpart[threadIdx.x];
            #pragma unroll
            for (int o = 4; o; o >>= 1) s += __shfl_down_sync(0xffu, s, o);
            if (threadIdx.x == 0) g_part[blockIdx.x] = s;
        }
    }

    const int t = idx >> 9;
    const int b = idx & 511;
    if (t >= 1) {
        const float tau = 0.005f;
        const float TM  = (float)(0.005 / 1.2);   // tau / mB
        const float UPT = (float)(1e-4 * 0.005);  // uP*IRzz*tau

        float dxm  = sc(l0.x, 0.16f);
        float dym  = sc(l0.y, 0.16f);
        float IBxx = sc(l0.w, 0.0123f);
        float IByy = sc(l1.x, 0.0123f);
        float IBzz = sc(l1.y, 0.0123f);
        float Cd   = sc(l1.z, 0.1f);
        float kTo  = sc(l2.x, 1.632e-07f);
        float tau2 = sc(l2.y, 0.015f);
        float kp   = sc(l2.z, 1.0f);
        float damp = sc(l2.w, 1.0f);

        float A    = (-2.0f * damp) * tau2;
        float Ap   = fmaf(tau, A, 1.0f);          // A' = 1 + tau*A
        float rt2s = __fdividef(1.0f, tau2 * tau2);
        float C1 = tau * ((kp * u1p[idx]) * rt2s);
        float C2 = tau * ((kp * u2p[idx]) * rt2s);
        float C3 = tau * ((kp * u3p[idx]) * rt2s);
        float C4 = tau * ((kp * u4p[idx]) * rt2s);

        float rx = __fdividef(1.0f, IBxx);
        float ry = __fdividef(1.0f, IByy);
        float rz = __fdividef(1.0f, IBzz);

        float Cdz   = Cd * TM;
        float kThz  = kTh * TM;
        float kThd1 = ((kTh * dym) * tau) * rx;
        float kThd2 = ((kTh * dxm) * tau) * ry;
        float e1 = ((IByy - IBzz) * tau) * rx;
        float u1 = UPT * rx;
        float e2 = ((IBzz - IBxx) * tau) * ry;
        float u2 = UPT * ry;
        float e3 = ((IBxx - IByy) * tau) * rz;
        float kToz = (kTo * tau) * rz;

        size_t o = (size_t)(t - 1) * B_DIM + b;
        g_pM0[o]  = make_float4(C1, C2, C3, C4);
        g_pM1[o]  = make_float4(Ap, minp[idx], maxp[idx], kThz);
        g_pR0[o]  = make_float4(e1, e2, -u1, u2);
        g_pR1[o]  = make_float4(kThd1, kThd2, e3, -kToz);
        g_pQ[o]   = make_float2(Cdz, lab[idx]);
    }
}

// ---------------------------------------------------------------------------
// Kernel 2: hover = sqrt(max(mB*g/(4*mean(kTh)+eps), 1e-6))
// ---------------------------------------------------------------------------
__global__ void hover_kernel()
{
    __shared__ double red[256];
    double s = 0.0;
    for (int i = threadIdx.x; i < PREP_BLOCKS; i += 256) s += (double)g_part[i];
    red[threadIdx.x] = s;
    __syncthreads();
    #pragma unroll
    for (int st = 128; st > 0; st >>= 1) {
        if (threadIdx.x < st) red[threadIdx.x] += red[threadIdx.x + st];
        __syncthreads();
    }
    if (threadIdx.x == 0) {
        float m   = (float)(red[0] / (double)NELEM);
        float den = 4.0f * m + 1e-12f;
        float v   = (float)(1.2 * 9.81) / den;
        v = fmaxf(v, 1e-6f);
        g_hover = sqrtf(v);
    }
}

// ---------------------------------------------------------------------------
// Kernel 3: warp-specialized 5-stage pipeline (R15 structure, IDENTICAL load
// streams & arithmetic) with SMSP steering via idle warps. 16 blocks x 256
// threads. SMSP = wid % 4:
//   SMSP0: wid0 Motors (24 ops/step)        — alone
//   SMSP1: wid1 Sums/Thr (13) + wid5 z/loss (17) = 30
//   SMSP2: wid2 Rates (18)                  — alone
//   SMSP3: wid3 Quaternion (16)             — alone
//   wid 4, 6, 7: idle (barrier loop only)
// ---------------------------------------------------------------------------
__global__ void __launch_bounds__(256, 1) sim_kernel(const float* __restrict__ labels)
{
    const int wid  = threadIdx.x >> 5;
    const int lane = threadIdx.x & 31;
    const int b    = blockIdx.x * 32 + lane;

    const float tau = 0.005f;
    const float HT  = 0.0025f;   // tau * 0.5
    const float GT  = 0.04905f;  // g * tau

    __shared__ float4 sW[2][WIN][32];   // w1c..w4c         W0 -> Sums
    __shared__ float4 sS[2][WIN][32];   // spp,smm,sqn,wsum Sums -> Rates
    __shared__ float  sT[4][WIN][32];   // Thr              Sums -> z/loss (3-win hop)
    __shared__ float4 sH[2][WIN][32];   // hp,hq,hr,0       Rates -> Quat
    __shared__ float4 sQ[2][WIN][32];   // pre-update q     Quat -> z/loss

    // batched prefetch bases (block-segment addressing)
    const char* pfM0 = (const char*)(g_pM0 + blockIdx.x * 32);
    const char* pfM1 = (const char*)(g_pM1 + blockIdx.x * 32);
    const char* pfR0 = (const char*)(g_pR0 + blockIdx.x * 32);
    const char* pfR1 = (const char*)(g_pR1 + blockIdx.x * 32);
    const char* pfQ  = (const char*)(g_pQ + blockIdx.x * 32);
    #define PF_F4(base, s0) PREFETCH_L2((base) + \
        (size_t)((s0) + 2 * WIN + (lane >> 2)) * 8192 + (size_t)(lane & 3) * 128)
    #define PF_F2(base, s0) if (lane < 16) PREFETCH_L2((base) + \
        (size_t)((s0) + 2 * WIN + (lane >> 1)) * 4096 + (size_t)(lane & 1) * 128)

    if (wid == 0) {
        // ================= Motors (window p) — SMSP0, alone =================
        const float hover = g_hover;
        float w1 = hover, w2 = hover, w3 = hover, w4 = hover;
        float wd1 = 0.f, wd2 = 0.f, wd3 = 0.f, wd4 = 0.f;
        const float4* __restrict__ PM0 = g_pM0 + b;
        const float4* __restrict__ PM1 = g_pM1 + b;
        float4 bm0[WIN], bm1[WIN];
        #pragma unroll
        for (int j = 0; j < WIN; ++j) {
            bm0[j] = PM0[(size_t)j * B_DIM];
            bm1[j] = PM1[(size_t)j * B_DIM];
        }
        for (int p = 0; p < NWIN + 4; ++p) {
            if (p < NWIN) {
                const int s0  = p * WIN;
                const int par = p & 1;
                PF_F4(pfM0, s0);
                PF_F4(pfM1, s0);
                #pragma unroll
                for (int j = 0; j < WIN; ++j) {
                    const float4 c0 = bm0[j];   // C1'..C4'
                    const float4 c1 = bm1[j];   // A', mn, mx, kThz
                    // nwd = A'*wd + (C' - tau*w)   [uses pre-clip w]
                    float t1 = fmaf(-tau, w1, c0.x);
                    float t2 = fmaf(-tau, w2, c0.y);
                    float t3 = fmaf(-tau, w3, c0.z);
                    float t4 = fmaf(-tau, w4, c0.w);

                    float w1c = fminf(fmaxf(w1, c1.y), c1.z);
                    float w2c = fminf(fmaxf(w2, c1.y), c1.z);
                    float w3c = fminf(fmaxf(w3, c1.y), c1.z);
                    float w4c = fminf(fmaxf(w4, c1.y), c1.z);

                    sW[par][j][lane] = make_float4(w1c, w2c, w3c, w4c);

                    w1 = fmaf(tau, wd1, w1c);
                    w2 = fmaf(tau, wd2, w2c);
                    w3 = fmaf(tau, wd3, w3c);
                    w4 = fmaf(tau, wd4, w4c);
                    wd1 = fmaf(c1.x, wd1, t1);
                    wd2 = fmaf(c1.x, wd2, t2);
                    wd3 = fmaf(c1.x, wd3, t3);
                    wd4 = fmaf(c1.x, wd4, t4);

                    bm0[j] = PM0[(size_t)(s0 + WIN + j) * B_DIM];
                    bm1[j] = PM1[(size_t)(s0 + WIN + j) * B_DIM];
                }
            }
            BARRIER();
        }
    } else if (wid == 1) {
        // ================= Sums / Thr (window p-1) — SMSP1 =================
        const float4* __restrict__ PM1 = g_pM1 + b;   // kThz in .w (L2/L1-hot)
        float4 bk[WIN];
        #pragma unroll
        for (int j = 0; j < WIN; ++j) bk[j] = PM1[(size_t)j * B_DIM];
        for (int p = 0; p < NWIN + 4; ++p) {
            if (p >= 1 && p <= NWIN) {
                const int w    = p - 1;
                const int s0   = w * WIN;
                const int par  = w & 1;
                const int par4 = w & 3;
                float4 wv[WIN];
                #pragma unroll
                for (int j = 0; j < WIN; ++j) wv[j] = sW[par][j][lane];
                #pragma unroll
                for (int j = 0; j < WIN; ++j) {
                    const float4 wc = wv[j];
                    float s1 = wc.x * wc.x, s2 = wc.y * wc.y;
                    float s3 = wc.z * wc.z, s4 = wc.w * wc.w;
                    float a12 = s1 + s2, a34 = s3 + s4;
                    float d12 = s1 - s2, d34 = s3 - s4;
                    float sa  = a12 + a34;
                    float spp = a12 - a34;
                    float smm = d12 - d34;
                    float sqn = d12 + d34;
                    float wsum = (wc.x - wc.y) + (wc.z - wc.w);
                    float Thr = bk[j].w * sa;

                    sS[par][j][lane]  = make_float4(spp, smm, sqn, wsum);
                    sT[par4][j][lane] = Thr;

                    bk[j] = PM1[(size_t)(s0 + WIN + j) * B_DIM];
                }
            }
            BARRIER();
        }
    } else if (wid == 2) {
        // ================= Body rates (window p-2) — SMSP2 =================
        float pv = 0.f, qv = 0.f, rv = 0.f;
        const float4* __restrict__ PR0 = g_pR0 + b;
        const float4* __restrict__ PR1 = g_pR1 + b;
        float4 br0[WIN], br1[WIN];
        #pragma unroll
        for (int j = 0; j < WIN; ++j) {
            br0[j] = PR0[(size_t)j * B_DIM];
            br1[j] = PR1[(size_t)j * B_DIM];
        }
        for (int p = 0; p < NWIN + 4; ++p) {
            if (p >= 2 && p <= NWIN + 1) {
                const int w   = p - 2;
                const int s0  = w * WIN;
                const int par = w & 1;
                PF_F4(pfR0, s0);
                PF_F4(pfR1, s0);
                float4 m[WIN];
                #pragma unroll
                for (int j = 0; j < WIN; ++j) m[j] = sS[par][j][lane];
                #pragma unroll
                for (int j = 0; j < WIN; ++j) {
                    const float4 r0 = br0[j];   // e1, e2, -u1, u2
                    const float4 r1 = br1[j];   // kThd1, kThd2, e3, -kToz
                    const float4 mm = m[j];     // spp, smm, sqn, wsum

                    float qvrv = qv * rv, pvrv = pv * rv, pvqv = pv * qv;
                    float wq = mm.w * qv, wp = mm.w * pv;

                    float t1 = r0.x * qvrv;
                    t1 = fmaf(r0.z, wq, t1);
                    t1 = fmaf(r1.x, mm.y, t1);
                    float npv = pv + t1;

                    float t2 = r0.y * pvrv;
                    t2 = fmaf(r0.w, wp, t2);
                    t2 = fmaf(r1.y, mm.x, t2);
                    float nqv = qv + t2;

                    float t3 = r1.z * pvqv;
                    t3 = fmaf(r1.w, mm.z, t3);
                    float nrv = rv + t3;

                    // half-rates from CURRENT (pre-update) state
                    float hp = HT * pv, hq = HT * qv, hr = HT * rv;
                    sH[par][j][lane] = make_float4(hp, hq, hr, 0.f);

                    pv = npv; qv = nqv; rv = nrv;

                    br0[j] = PR0[(size_t)(s0 + WIN + j) * B_DIM];
                    br1[j] = PR1[(size_t)(s0 + WIN + j) * B_DIM];
                }
            }
            BARRIER();
        }
    } else if (wid == 3) {
        // ================= Quaternion (window p-3) — SMSP3 =================
        float q0 = 1.f, q1 = 0.f, q2 = 0.f, q3 = 0.f;
        for (int p = 0; p < NWIN + 4; ++p) {
            if (p >= 3 && p <= NWIN + 2) {
                const int w   = p - 3;
                const int par = w & 1;
                float4 h[WIN];
                #pragma unroll
                for (int j = 0; j < WIN; ++j) h[j] = sH[par][j][lane];
                #pragma unroll
                for (int j = 0; j < WIN; ++j) {
                    const float hp = h[j].x, hq = h[j].y, hr = h[j].z;

                    // pre-update q goes to z/loss (z-dynamics uses carry q)
                    sQ[par][j][lane] = make_float4(q0, q1, q2, q3);

                    float tA0 = fmaf(-hr, q3, fmaf(-hq, q2, (-hp) * q1));
                    float tA2 = fmaf(-hr, q1, fmaf( hq, q0,   hp  * q3));
                    float tB1 = fmaf( hr, q2, fmaf(-hq, q3,   hp  * q0));
                    float tB3 = fmaf( hr, q0, fmaf( hq, q1, (-hp) * q2));
                    float nq0 = q0 + tA0;
                    float nq2 = q2 + tA2;
                    float nq1 = q1 + tB1;
                    float nq3 = q3 + tB3;
                    q0 = nq0; q1 = nq1; q2 = nq2; q3 = nq3;
                }
            }
            BARRIER();
        }
    } else if (wid == 5) {
        // ================= z / loss (window p-4) — SMSP1 =================
        float xz = 0.f, zd = 0.f;
        const float2* __restrict__ PQ = g_pQ + b;
        float2 bq[WIN];
        #pragma unroll
        for (int j = 0; j < WIN; ++j) bq[j] = PQ[(size_t)j * B_DIM];
        double acc;
        { float l0 = labels[b]; acc = (double)l0 * (double)l0; }
        for (int p = 0; p < NWIN + 4; ++p) {
            if (p >= 4) {
                const int w    = p - 4;
                const int s0   = w * WIN;
                const int par  = w & 1;
                const int par4 = w & 3;
                PF_F2(pfQ, s0);
                float4 qv4[WIN];
                float  thr[WIN];
                #pragma unroll
                for (int j = 0; j < WIN; ++j) {
                    qv4[j] = sQ[par][j][lane];
                    thr[j] = sT[par4][j][lane];
                }
                float accf = 0.f;
                #pragma unroll
                for (int j = 0; j < WIN; ++j) {
                    const float2 qc = bq[j];        // Cd', label
                    const float4 qd = qv4[j];
                    const float Thr = thr[j];

                    float sq0 = qd.x * qd.x, sq1 = qd.y * qd.y;
                    float sq2 = qd.z * qd.z, sq3 = qd.w * qd.w;
                    float qq = (sq0 - sq1) - (sq2 - sq3);

                    float zd2 = zd * zd;
                    float sz = (zd > 0.f) ? 1.f : ((zd < 0.f) ? -1.f : 0.f);
                    float drag = qc.x * (sz * zd2);
                    float nzd = zd + ((Thr * qq - drag) - GT);

                    float nxz_raw = fmaf(tau, nzd, xz);
                    float diff = nxz_raw - xz;
                    float nxz = (fabsf(diff) <= 400.0f) ? nxz_raw : xz;

                    float dz = nxz - qc.y;
                    if (s0 + j < NSTEP) accf = fmaf(dz, dz, accf);

                    xz = nxz; zd = nzd;

                    bq[j] = PQ[(size_t)(s0 + WIN + j) * B_DIM];
                }
                acc += (double)accf;
            }
            BARRIER();
        }
        g_loss[b] = acc;
    } else {
        // ================= idle warps (wid 4, 6, 7) =================
        for (int p = 0; p < NWIN + 4; ++p) BARRIER();
    }
    #undef PF_F4
    #undef PF_F2
}

// ---------------------------------------------------------------------------
// Kernel 4: deterministic loss reduction -> mean
// ---------------------------------------------------------------------------
__global__ void loss_kernel(float* __restrict__ out)
{
    __shared__ double red[B_DIM];
    red[threadIdx.x] = g_loss[threadIdx.x];
    __syncthreads();
    #pragma unroll
    for (int s = 256; s > 0; s >>= 1) {
        if (threadIdx.x < s) red[threadIdx.x] += red[threadIdx.x + s];
        __syncthreads();
    }
    if (threadIdx.x == 0) out[0] = (float)(red[0] / (double)NELEM);
}

// ---------------------------------------------------------------------------
// Launch
// ---------------------------------------------------------------------------
extern "C" void kernel_launch(void* const* d_in, const int* in_sizes, int n_in,
                              void* d_out, int out_size)
{
    const float* labels = (const float*)d_in[0];
    const float* logits = (const float*)d_in[1];
    const float* u1     = (const float*)d_in[2];
    const float* u2     = (const float*)d_in[3];
    const float* u3     = (const float*)d_in[4];
    const float* u4     = (const float*)d_in[5];
    const float* maxM   = (const float*)d_in[6];
    const float* minM   = (const float*)d_in[7];

    prep_kernel<<<PREP_BLOCKS, 256>>>(logits, u1, u2, u3, u4, maxM, minM, labels);
    hover_kernel<<<1, 256>>>();
    sim_kernel<<<16, 256>>>(labels);
    loss_kernel<<<1, B_DIM>>>((float*)d_out);
}